// round 7
// baseline (speedup 1.0000x reference)
#include <cuda_runtime.h>

#define BB 4
#define NN 16384
#define SSZ 2048            // queries per batch (NEVENT)
#define DD 62
#define CC 64               // D + 2
#define KK 64               // NSAMPLE
#define NQ (BB*SSZ)         // 8192 total queries
#define MMM 8388608         // SSZ*KK*CC per batch
#define R2 0.01f
#define CH1 24              // K1 scans at most CH1 chunks of 128 pts (3072)
#define PHASE_PTS (CH1*128)

// ---- scratch (device globals; fully overwritten every launch) ----
__device__ int    g_idx[NQ*KK];     // neighbor indices
__device__ int    g_cnt[NQ];        // hit count after K1 (>=KK means finished)
__device__ float4 g_mean4[NQ*16];   // per-(query,channel) means
__device__ float  g_ss[NQ];         // per-query sum of squared centered
__device__ float  g_rstd[BB];       // 1/(std+1e-5) per batch

// ---------------------------------------------------------------------------
// Stats helpers (warp-collective, lane = channel pair; fixed-order reductions)
// ---------------------------------------------------------------------------
__device__ __forceinline__ void stats1(int q, const int* sidx, int lane,
                                       const float2* xyb, const float2* evb2)
{
    float2 s1 = make_float2(0.f,0.f), s2 = make_float2(0.f,0.f);
    bool isxy = (lane == 31);
    #pragma unroll 8
    for (int k = 0; k < KK; k++) {
        int j = sidx[k];
        float2 v = isxy ? xyb[j] : evb2[(size_t)j * 31 + lane];
        s1.x += v.x; s1.y += v.y;
        s2.x = fmaf(v.x, v.x, s2.x);
        s2.y = fmaf(v.y, v.y, s2.y);
    }
    float2 m = make_float2(s1.x * (1.0f/64.0f), s1.y * (1.0f/64.0f));
    reinterpret_cast<float2*>(g_mean4)[(size_t)q * 32 + lane] = m;
    float ss = (s2.x - s1.x * m.x) + (s2.y - s1.y * m.y);
    #pragma unroll
    for (int off = 16; off >= 1; off >>= 1)
        ss += __shfl_down_sync(0xffffffffu, ss, off);
    if (lane == 0) g_ss[q] = ss;
}

__device__ __forceinline__ void stats2(int q0, int q1, const int* s0, const int* s1i,
                                       int lane, const float2* xyb, const float2* evb2)
{
    float2 s1a = make_float2(0.f,0.f), s2a = make_float2(0.f,0.f);
    float2 s1b = make_float2(0.f,0.f), s2b = make_float2(0.f,0.f);
    bool isxy = (lane == 31);
    #pragma unroll 8
    for (int k = 0; k < KK; k++) {
        int ja = s0[k], jb = s1i[k];
        float2 va = isxy ? xyb[ja] : evb2[(size_t)ja * 31 + lane];
        float2 vb = isxy ? xyb[jb] : evb2[(size_t)jb * 31 + lane];
        s1a.x += va.x; s1a.y += va.y;
        s2a.x = fmaf(va.x, va.x, s2a.x);
        s2a.y = fmaf(va.y, va.y, s2a.y);
        s1b.x += vb.x; s1b.y += vb.y;
        s2b.x = fmaf(vb.x, vb.x, s2b.x);
        s2b.y = fmaf(vb.y, vb.y, s2b.y);
    }
    float2 ma = make_float2(s1a.x * (1.0f/64.0f), s1a.y * (1.0f/64.0f));
    float2 mb = make_float2(s1b.x * (1.0f/64.0f), s1b.y * (1.0f/64.0f));
    reinterpret_cast<float2*>(g_mean4)[(size_t)q0 * 32 + lane] = ma;
    reinterpret_cast<float2*>(g_mean4)[(size_t)q1 * 32 + lane] = mb;
    float ssa = (s2a.x - s1a.x * ma.x) + (s2a.y - s1a.y * ma.y);
    float ssb = (s2b.x - s1b.x * mb.x) + (s2b.y - s1b.y * mb.y);
    #pragma unroll
    for (int off = 16; off >= 1; off >>= 1) {
        ssa += __shfl_down_sync(0xffffffffu, ssa, off);
        ssb += __shfl_down_sync(0xffffffffu, ssb, off);
    }
    if (lane == 0) { g_ss[q0] = ssa; g_ss[q1] = ssb; }
}

// ---------------------------------------------------------------------------
// K1: uniform phase — ball query over at most PHASE_PTS points, 2 queries per
// warp sharing one candidate stream. Finished queries get stats here; the
// unfinished (~15%, edge/corner) persist cnt + partial indices for K2.
// Distance replicates reference fp32 op sequence exactly (see R1 notes).
// ---------------------------------------------------------------------------
__global__ __launch_bounds__(128) void k_phase1(
    const float* __restrict__ xy, const float* __restrict__ ev,
    const int* __restrict__ fps, float* __restrict__ out_xy, int write_xy)
{
    int w    = threadIdx.x >> 5;
    int lane = threadIdx.x & 31;
    int q0   = blockIdx.x * 8 + w * 2;
    int q1   = q0 + 1;
    int b    = q0 >> 11;

    __shared__ int sidx[4][2][KK];

    const float2* xyb  = reinterpret_cast<const float2*>(xy) + (size_t)b * NN;
    const float4* xyb4 = reinterpret_cast<const float4*>(xyb);

    float2 qa = xyb[fps[q0]];
    float2 qb = xyb[fps[q1]];
    float qna = __fadd_rn(__fmul_rn(qa.x, qa.x), __fmul_rn(qa.y, qa.y));
    float qnb = __fadd_rn(__fmul_rn(qb.x, qb.x), __fmul_rn(qb.y, qb.y));
    if (write_xy && lane == 0) {
        out_xy[2*q0] = qa.x; out_xy[2*q0+1] = qa.y;
        out_xy[2*q1] = qb.x; out_xy[2*q1+1] = qb.y;
    }

    unsigned lmask = (1u << lane) - 1u;
    int cnt0 = 0, cnt1 = 0;
    float4 fa = xyb4[2*lane];
    float4 fb = xyb4[2*lane + 1];
    for (int ch = 0; ch < CH1; ch++) {
        bool more = (ch + 1 < CH1);
        float4 na, nb;
        if (more) {
            na = xyb4[(ch+1)*64 + 2*lane];
            nb = xyb4[(ch+1)*64 + 2*lane + 1];
        }
        float pn0 = __fadd_rn(__fmul_rn(fa.x, fa.x), __fmul_rn(fa.y, fa.y));
        float pn1 = __fadd_rn(__fmul_rn(fa.z, fa.z), __fmul_rn(fa.w, fa.w));
        float pn2 = __fadd_rn(__fmul_rn(fb.x, fb.x), __fmul_rn(fb.y, fb.y));
        float pn3 = __fadd_rn(__fmul_rn(fb.z, fb.z), __fmul_rn(fb.w, fb.w));
        int base = ch*128 + 4*lane;

        if (cnt0 < KK) {
            float c0 = __fmaf_rn(qa.y, fa.y, __fmul_rn(qa.x, fa.x));
            float c1 = __fmaf_rn(qa.y, fa.w, __fmul_rn(qa.x, fa.z));
            float c2 = __fmaf_rn(qa.y, fb.y, __fmul_rn(qa.x, fb.x));
            float c3 = __fmaf_rn(qa.y, fb.w, __fmul_rn(qa.x, fb.z));
            bool h0 = !(__fsub_rn(__fadd_rn(qna, pn0), __fmul_rn(2.0f, c0)) > R2);
            bool h1 = !(__fsub_rn(__fadd_rn(qna, pn1), __fmul_rn(2.0f, c1)) > R2);
            bool h2 = !(__fsub_rn(__fadd_rn(qna, pn2), __fmul_rn(2.0f, c2)) > R2);
            bool h3 = !(__fsub_rn(__fadd_rn(qna, pn3), __fmul_rn(2.0f, c3)) > R2);
            unsigned m0 = __ballot_sync(0xffffffffu, h0);
            unsigned m1 = __ballot_sync(0xffffffffu, h1);
            unsigned m2 = __ballot_sync(0xffffffffu, h2);
            unsigned m3 = __ballot_sync(0xffffffffu, h3);
            int pos = cnt0 + __popc(m0 & lmask) + __popc(m1 & lmask)
                           + __popc(m2 & lmask) + __popc(m3 & lmask);
            if (h0 && pos < KK) sidx[w][0][pos] = base;
            pos += h0 ? 1 : 0;
            if (h1 && pos < KK) sidx[w][0][pos] = base + 1;
            pos += h1 ? 1 : 0;
            if (h2 && pos < KK) sidx[w][0][pos] = base + 2;
            pos += h2 ? 1 : 0;
            if (h3 && pos < KK) sidx[w][0][pos] = base + 3;
            cnt0 += __popc(m0) + __popc(m1) + __popc(m2) + __popc(m3);
        }
        if (cnt1 < KK) {
            float c0 = __fmaf_rn(qb.y, fa.y, __fmul_rn(qb.x, fa.x));
            float c1 = __fmaf_rn(qb.y, fa.w, __fmul_rn(qb.x, fa.z));
            float c2 = __fmaf_rn(qb.y, fb.y, __fmul_rn(qb.x, fb.x));
            float c3 = __fmaf_rn(qb.y, fb.w, __fmul_rn(qb.x, fb.z));
            bool h0 = !(__fsub_rn(__fadd_rn(qnb, pn0), __fmul_rn(2.0f, c0)) > R2);
            bool h1 = !(__fsub_rn(__fadd_rn(qnb, pn1), __fmul_rn(2.0f, c1)) > R2);
            bool h2 = !(__fsub_rn(__fadd_rn(qnb, pn2), __fmul_rn(2.0f, c2)) > R2);
            bool h3 = !(__fsub_rn(__fadd_rn(qnb, pn3), __fmul_rn(2.0f, c3)) > R2);
            unsigned m0 = __ballot_sync(0xffffffffu, h0);
            unsigned m1 = __ballot_sync(0xffffffffu, h1);
            unsigned m2 = __ballot_sync(0xffffffffu, h2);
            unsigned m3 = __ballot_sync(0xffffffffu, h3);
            int pos = cnt1 + __popc(m0 & lmask) + __popc(m1 & lmask)
                           + __popc(m2 & lmask) + __popc(m3 & lmask);
            if (h0 && pos < KK) sidx[w][1][pos] = base;
            pos += h0 ? 1 : 0;
            if (h1 && pos < KK) sidx[w][1][pos] = base + 1;
            pos += h1 ? 1 : 0;
            if (h2 && pos < KK) sidx[w][1][pos] = base + 2;
            pos += h2 ? 1 : 0;
            if (h3 && pos < KK) sidx[w][1][pos] = base + 3;
            cnt1 += __popc(m0) + __popc(m1) + __popc(m2) + __popc(m3);
        }
        if (cnt0 >= KK && cnt1 >= KK) break;
        fa = na; fb = nb;
    }
    __syncwarp();

    bool done0 = (cnt0 >= KK), done1 = (cnt1 >= KK);
    if (lane == 0) { g_cnt[q0] = cnt0; g_cnt[q1] = cnt1; }

    if (done0) {
        g_idx[(size_t)q0 * KK + lane]      = sidx[w][0][lane];
        g_idx[(size_t)q0 * KK + lane + 32] = sidx[w][0][lane + 32];
    } else {
        for (int p = lane; p < cnt0; p += 32)
            g_idx[(size_t)q0 * KK + p] = sidx[w][0][p];
    }
    if (done1) {
        g_idx[(size_t)q1 * KK + lane]      = sidx[w][1][lane];
        g_idx[(size_t)q1 * KK + lane + 32] = sidx[w][1][lane + 32];
    } else {
        for (int p = lane; p < cnt1; p += 32)
            g_idx[(size_t)q1 * KK + p] = sidx[w][1][p];
    }

    const float2* evb2 = reinterpret_cast<const float2*>(ev + (size_t)b * NN * DD);
    if (done0 && done1)      stats2(q0, q1, sidx[w][0], sidx[w][1], lane, xyb, evb2);
    else if (done0)          stats1(q0, sidx[w][0], lane, xyb, evb2);
    else if (done1)          stats1(q1, sidx[w][1], lane, xyb, evb2);
}

// ---------------------------------------------------------------------------
// K2: tail phase — warp per query; most warps read g_cnt >= 64 and exit.
// Stragglers resume the scan at PHASE_PTS, finish compaction, pad, stats.
// ---------------------------------------------------------------------------
__global__ __launch_bounds__(128) void k_tail(
    const float* __restrict__ xy, const float* __restrict__ ev,
    const int* __restrict__ fps)
{
    int w    = threadIdx.x >> 5;
    int lane = threadIdx.x & 31;
    int q    = blockIdx.x * 4 + w;
    int b    = q >> 11;

    int cnt = g_cnt[q];
    if (cnt >= KK) return;

    __shared__ int sidx[4][KK];
    for (int p = lane; p < cnt; p += 32) sidx[w][p] = g_idx[(size_t)q * KK + p];
    __syncwarp();

    const float2* xyb  = reinterpret_cast<const float2*>(xy) + (size_t)b * NN;
    const float4* xyb4 = reinterpret_cast<const float4*>(xyb);

    float2 qp = xyb[fps[q]];
    float qn = __fadd_rn(__fmul_rn(qp.x, qp.x), __fmul_rn(qp.y, qp.y));

    unsigned lmask = (1u << lane) - 1u;
    float4 fa = xyb4[(PHASE_PTS >> 1) + 2*lane];
    float4 fb = xyb4[(PHASE_PTS >> 1) + 2*lane + 1];
    for (int j0 = PHASE_PTS; ; j0 += 128) {
        int jn = j0 + 128;
        bool more = (jn < NN);
        float4 na, nb;
        if (more) {
            na = xyb4[(jn >> 1) + 2*lane];
            nb = xyb4[(jn >> 1) + 2*lane + 1];
        }
        float pn0 = __fadd_rn(__fmul_rn(fa.x, fa.x), __fmul_rn(fa.y, fa.y));
        float c0  = __fmaf_rn(qp.y, fa.y, __fmul_rn(qp.x, fa.x));
        bool  h0  = !(__fsub_rn(__fadd_rn(qn, pn0), __fmul_rn(2.0f, c0)) > R2);
        float pn1 = __fadd_rn(__fmul_rn(fa.z, fa.z), __fmul_rn(fa.w, fa.w));
        float c1  = __fmaf_rn(qp.y, fa.w, __fmul_rn(qp.x, fa.z));
        bool  h1  = !(__fsub_rn(__fadd_rn(qn, pn1), __fmul_rn(2.0f, c1)) > R2);
        float pn2 = __fadd_rn(__fmul_rn(fb.x, fb.x), __fmul_rn(fb.y, fb.y));
        float c2  = __fmaf_rn(qp.y, fb.y, __fmul_rn(qp.x, fb.x));
        bool  h2  = !(__fsub_rn(__fadd_rn(qn, pn2), __fmul_rn(2.0f, c2)) > R2);
        float pn3 = __fadd_rn(__fmul_rn(fb.z, fb.z), __fmul_rn(fb.w, fb.w));
        float c3  = __fmaf_rn(qp.y, fb.w, __fmul_rn(qp.x, fb.z));
        bool  h3  = !(__fsub_rn(__fadd_rn(qn, pn3), __fmul_rn(2.0f, c3)) > R2);

        unsigned m0 = __ballot_sync(0xffffffffu, h0);
        unsigned m1 = __ballot_sync(0xffffffffu, h1);
        unsigned m2 = __ballot_sync(0xffffffffu, h2);
        unsigned m3 = __ballot_sync(0xffffffffu, h3);
        int pos = cnt + __popc(m0 & lmask) + __popc(m1 & lmask)
                      + __popc(m2 & lmask) + __popc(m3 & lmask);
        int base = j0 + 4*lane;
        if (h0 && pos < KK) sidx[w][pos] = base;
        pos += h0 ? 1 : 0;
        if (h1 && pos < KK) sidx[w][pos] = base + 1;
        pos += h1 ? 1 : 0;
        if (h2 && pos < KK) sidx[w][pos] = base + 2;
        pos += h2 ? 1 : 0;
        if (h3 && pos < KK) sidx[w][pos] = base + 3;
        cnt += __popc(m0) + __popc(m1) + __popc(m2) + __popc(m3);
        if (cnt >= KK || !more) break;
        fa = na; fb = nb;
    }
    __syncwarp();
    if (cnt < KK) {                       // pad with first hit (cnt>=1: self-hit)
        int f0 = sidx[w][0];
        for (int p = cnt + lane; p < KK; p += 32) sidx[w][p] = f0;
        __syncwarp();
    }

    g_idx[(size_t)q * KK + lane]      = sidx[w][lane];
    g_idx[(size_t)q * KK + lane + 32] = sidx[w][lane + 32];

    const float2* evb2 = reinterpret_cast<const float2*>(ev + (size_t)b * NN * DD);
    stats1(q, sidx[w], lane, xyb, evb2);
}

// ---------------------------------------------------------------------------
// K_B: per-batch SS reduce -> rstd. One block per batch, fixed-order tree.
// ---------------------------------------------------------------------------
__global__ __launch_bounds__(256) void k_finalize()
{
    int b = blockIdx.x, t = threadIdx.x;
    __shared__ float sh[256];
    float s = 0.f;
    #pragma unroll
    for (int i = 0; i < 8; i++) s += g_ss[(size_t)b * SSZ + t*8 + i];
    sh[t] = s;
    __syncthreads();
    for (int off = 128; off >= 1; off >>= 1) {
        if (t < off) sh[t] += sh[t + off];
        __syncthreads();
    }
    if (t == 0) {
        float var = sh[0] / (float)(MMM - 1);   // ddof = 1
        g_rstd[b] = 1.0f / (sqrtf(var) + 1e-5f);
    }
}

// ---------------------------------------------------------------------------
// K_C: regather + normalize + affine. Block per query. float4 stores.
// ---------------------------------------------------------------------------
__global__ __launch_bounds__(256) void k_write(
    const float* __restrict__ xy, const float* __restrict__ ev,
    const float* __restrict__ alpha, const float* __restrict__ beta,
    float* __restrict__ out_ev)
{
    int q = blockIdx.x;
    int b = q >> 11;
    int t = threadIdx.x;
    int c4 = t & 15, kg = t >> 4;

    __shared__ int    sidx[KK];
    __shared__ float4 smean[16], sal[16], sbe[16];

    if (t < 64)        sidx[t]     = g_idx[(size_t)q * KK + t];
    else if (t < 80)   smean[t-64] = g_mean4[(size_t)q * 16 + (t-64)];
    else if (t < 96)   sal[t-80]   = reinterpret_cast<const float4*>(alpha)[t-80];
    else if (t < 112)  sbe[t-96]   = reinterpret_cast<const float4*>(beta)[t-96];
    __syncthreads();

    float  rstd = g_rstd[b];
    float4 mean = smean[c4];
    float4 al   = sal[c4];
    float4 be   = sbe[c4];

    const float2* evb2 = reinterpret_cast<const float2*>(ev + (size_t)b * NN * DD);
    const float2* xyb  = reinterpret_cast<const float2*>(xy) + (size_t)b * NN;
    float4* op = reinterpret_cast<float4*>(out_ev) + (size_t)q * KK * 16;

    #pragma unroll
    for (int ki = 0; ki < 4; ki++) {
        int k = ki * 16 + kg;
        int j = sidx[k];
        float2 va, vb;
        if (c4 < 15) {
            va = evb2[(size_t)j * 31 + 2*c4];
            vb = evb2[(size_t)j * 31 + 2*c4 + 1];
        } else {
            va = evb2[(size_t)j * 31 + 30];    // channels 60,61
            vb = xyb[j];                        // channels 62,63
        }
        float4 r;
        r.x = fmaf(al.x, (va.x - mean.x) * rstd, be.x);
        r.y = fmaf(al.y, (va.y - mean.y) * rstd, be.y);
        r.z = fmaf(al.z, (vb.x - mean.z) * rstd, be.z);
        r.w = fmaf(al.w, (vb.y - mean.w) * rstd, be.w);
        op[(size_t)k * 16 + c4] = r;
    }
}

// ---------------------------------------------------------------------------
extern "C" void kernel_launch(void* const* d_in, const int* in_sizes, int n_in,
                              void* d_out, int out_size)
{
    const float* xy    = (const float*)d_in[0];
    const float* ev    = (const float*)d_in[1];
    const int*   fps   = (const int*)d_in[2];
    const float* alpha = (const float*)d_in[3];
    const float* beta  = (const float*)d_in[4];
    float* out = (float*)d_out;

    long long ev_elems = (long long)NQ * KK * CC;
    int has_xy = ((long long)out_size >= ev_elems + (long long)NQ * 2) ? 1 : 0;
    float* out_ev = out + (has_xy ? NQ * 2 : 0);

    k_phase1  <<<NQ/8, 128>>>(xy, ev, fps, out, has_xy);
    k_tail    <<<NQ/4, 128>>>(xy, ev, fps);
    k_finalize<<<BB,   256>>>();
    k_write   <<<NQ,   256>>>(xy, ev, alpha, beta, out_ev);
}